// round 1
// baseline (speedup 1.0000x reference)
#include <cuda_runtime.h>
#include <math.h>

// ---------------- Problem constants ----------------
#define NHEADS   128
#define DNOPE    128
#define DROPE    64
#define DQK      576      // 512 + 64
#define RKV      512
#define RQ       1536
#define HID      5120
#define QLEN     256
#define SLEN     4096
#define QB_COLS  24576    // NH*(DNOPE+DROPE)
#define AO_COLS  16384    // NH*DNOPE
#define EPSF     1e-6f

// ---------------- Scratch (device globals; no allocation allowed) ----------------
__device__ float g_qa_buf   [QLEN * RQ];                       // 256x1536
__device__ float g_qfull    [QLEN * QB_COLS];                  // 256x24576
__device__ float g_ckvraw   [SLEN * DQK];                      // 4096x576
__device__ float g_Kc       [SLEN * DQK];                      // normed ckv + roped k_pe
__device__ float g_Qc       [(size_t)NHEADS * QLEN * DQK];     // per-head q_c + roped q_pe
__device__ float g_logits   [(size_t)NHEADS * QLEN * SLEN];    // 512 MB
__device__ float g_oc       [(size_t)NHEADS * QLEN * RKV];     // per-head o_c
__device__ float g_ao       [QLEN * AO_COLS];                  // 256x16384

// ---------------- Generic tiled fp32 GEMM ----------------
// C[M,N] = A[M,K] @ B  (TRANSB=0: B is [K,N]; TRANSB=1: B is [N,K], C=A@B^T)
// All of M,N %64==0 and K%16==0 for every call in this problem (verified).
// Batched over gridDim.z with element strides sA/sB/sC.
template<bool TRANSB>
__global__ void __launch_bounds__(256) gemm_tile(
    const float* __restrict__ A, const float* __restrict__ B, float* __restrict__ C,
    int M, int N, int K, int lda, int ldb, int ldc,
    long sA, long sB, long sC)
{
    A += (long)blockIdx.z * sA;
    B += (long)blockIdx.z * sB;
    C += (long)blockIdx.z * sC;

    __shared__ float As[16][68];   // [k][m], padded
    __shared__ float Bs[16][68];   // [k][n], padded

    const int tid = threadIdx.x;
    const int tx = tid & 15;       // n micro index
    const int ty = tid >> 4;       // m micro index
    const int bm = blockIdx.y * 64;
    const int bn = blockIdx.x * 64;

    float acc[4][4];
#pragma unroll
    for (int i = 0; i < 4; i++)
#pragma unroll
        for (int j = 0; j < 4; j++) acc[i][j] = 0.f;

    const int arow = tid >> 2;            // 0..63
    const int ac4  = (tid & 3) * 4;       // 0,4,8,12
    const int brow_nn = tid >> 4;         // 0..15 (k row)
    const int bc4_nn  = (tid & 15) * 4;   // n col
    const int brow_nt = tid >> 2;         // 0..63 (n row)
    const int bc4_nt  = (tid & 3) * 4;    // k col

    for (int k0 = 0; k0 < K; k0 += 16) {
        // load A tile (64 x 16), store transposed
        float4 av = *(const float4*)&A[(long)(bm + arow) * lda + (k0 + ac4)];
        As[ac4 + 0][arow] = av.x;
        As[ac4 + 1][arow] = av.y;
        As[ac4 + 2][arow] = av.z;
        As[ac4 + 3][arow] = av.w;

        if (TRANSB) {
            float4 bv = *(const float4*)&B[(long)(bn + brow_nt) * ldb + (k0 + bc4_nt)];
            Bs[bc4_nt + 0][brow_nt] = bv.x;
            Bs[bc4_nt + 1][brow_nt] = bv.y;
            Bs[bc4_nt + 2][brow_nt] = bv.z;
            Bs[bc4_nt + 3][brow_nt] = bv.w;
        } else {
            float4 bv = *(const float4*)&B[(long)(k0 + brow_nn) * ldb + (bn + bc4_nn)];
            *(float4*)&Bs[brow_nn][bc4_nn] = bv;
        }
        __syncthreads();

#pragma unroll
        for (int kk = 0; kk < 16; kk++) {
            float4 a = *(const float4*)&As[kk][ty * 4];
            float4 b = *(const float4*)&Bs[kk][tx * 4];
            float ar[4] = {a.x, a.y, a.z, a.w};
            float br[4] = {b.x, b.y, b.z, b.w};
#pragma unroll
            for (int i = 0; i < 4; i++)
#pragma unroll
                for (int j = 0; j < 4; j++)
                    acc[i][j] = fmaf(ar[i], br[j], acc[i][j]);
        }
        __syncthreads();
    }

#pragma unroll
    for (int i = 0; i < 4; i++) {
        int m = bm + ty * 4 + i;
        float4 v = make_float4(acc[i][0], acc[i][1], acc[i][2], acc[i][3]);
        *(float4*)&C[(long)m * ldc + bn + tx * 4] = v;
    }
}

// ---------------- RMSNorm (in place), one block per row ----------------
__global__ void rmsnorm_rows(float* __restrict__ X, const float* __restrict__ g, int cols)
{
    const long row = blockIdx.x;
    float* x = X + row * (long)cols;
    const int tid = threadIdx.x;
    float ss = 0.f;
    for (int c = tid; c < cols; c += blockDim.x) { float v = x[c]; ss += v * v; }
    __shared__ float red[256];
    red[tid] = ss; __syncthreads();
    for (int s = 128; s > 0; s >>= 1) { if (tid < s) red[tid] += red[tid + s]; __syncthreads(); }
    const float inv = rsqrtf(red[0] / (float)cols + EPSF);
    for (int c = tid; c < cols; c += blockDim.x) x[c] = x[c] * inv * g[c];
}

// ---------------- Build K_comb: rmsnorm(ckv) into [0:512), roped k_pe into [512:576) ----------------
__global__ void build_K(const float* __restrict__ raw, const float* __restrict__ g,
                        const int* __restrict__ kvpos, float* __restrict__ Kc)
{
    const int s = blockIdx.x;
    const float* r = raw + (long)s * DQK;
    float* k = Kc + (long)s * DQK;
    const int tid = threadIdx.x;   // 128

    float ss = 0.f;
    for (int c = tid; c < RKV; c += 128) { float v = r[c]; ss += v * v; }
    __shared__ float red[128];
    red[tid] = ss; __syncthreads();
    for (int st = 64; st > 0; st >>= 1) { if (tid < st) red[tid] += red[tid + st]; __syncthreads(); }
    const float inv = rsqrtf(red[0] / (float)RKV + EPSF);
    for (int c = tid; c < RKV; c += 128) k[c] = r[c] * inv * g[c];

    if (tid < 32) {
        const int j = tid;
        const float x0 = r[RKV + 2 * j];
        const float x1 = r[RKV + 2 * j + 1];
        const float pos = (float)kvpos[s];
        const float invf = powf(10000.f, -(float)j / 32.f);
        const float ang = pos * invf;
        float cs, sn; sincosf(ang, &sn, &cs);
        k[RKV + j]       = x0 * cs - x1 * sn;
        k[RKV + 32 + j]  = x0 * sn + x1 * cs;
    }
}

// ---------------- RoPE for q_pe, writes into Q_comb[h][t][512:576) ----------------
__global__ void rope_Q(const float* __restrict__ qfull, const int* __restrict__ qpos,
                       float* __restrict__ Qc)
{
    const int t = blockIdx.x;
    const int h = blockIdx.y;
    const int j = threadIdx.x;   // 32
    const float* src = qfull + (long)t * QB_COLS + h * (DNOPE + DROPE) + DNOPE;
    const float x0 = src[2 * j];
    const float x1 = src[2 * j + 1];
    const float pos = (float)qpos[t];
    const float invf = powf(10000.f, -(float)j / 32.f);
    const float ang = pos * invf;
    float cs, sn; sincosf(ang, &sn, &cs);
    float* dst = Qc + ((long)h * QLEN + t) * DQK + RKV;
    dst[j]      = x0 * cs - x1 * sn;
    dst[32 + j] = x0 * sn + x1 * cs;
}

// ---------------- Row softmax with scale folded in ----------------
__global__ void softmax_rows(float* __restrict__ X, int cols, float scale)
{
    const long row = blockIdx.x;
    float* x = X + row * (long)cols;
    const int tid = threadIdx.x;   // 256
    __shared__ float red[256];

    float m = -INFINITY;
    for (int c = tid; c < cols; c += 256) m = fmaxf(m, x[c]);
    red[tid] = m; __syncthreads();
    for (int s = 128; s > 0; s >>= 1) { if (tid < s) red[tid] = fmaxf(red[tid], red[tid + s]); __syncthreads(); }
    m = red[0]; __syncthreads();

    float sum = 0.f;
    for (int c = tid; c < cols; c += 256) {
        float p = __expf((x[c] - m) * scale);
        x[c] = p;
        sum += p;
    }
    red[tid] = sum; __syncthreads();
    for (int s = 128; s > 0; s >>= 1) { if (tid < s) red[tid] += red[tid + s]; __syncthreads(); }
    const float invs = 1.f / red[0];
    for (int c = tid; c < cols; c += 256) x[c] *= invs;
}

// ---------------- Launch ----------------
static inline float* sym(const void* s)
{
    void* p = nullptr;
    cudaGetSymbolAddress(&p, s);
    return (float*)p;
}

extern "C" void kernel_launch(void* const* d_in, const int* in_sizes, int n_in,
                              void* d_out, int out_size)
{
    const float* hq    = (const float*)d_in[0];
    const float* hkv   = (const float*)d_in[1];
    const float* W_qa  = (const float*)d_in[2];
    const float* gqa   = (const float*)d_in[3];
    const float* W_qb  = (const float*)d_in[4];
    const float* W_kva = (const float*)d_in[5];
    const float* gkva  = (const float*)d_in[6];
    const float* W_kvb = (const float*)d_in[7];
    const float* W_o   = (const float*)d_in[8];
    const int*   qpos  = (const int*)d_in[9];
    const int*   kvpos = (const int*)d_in[10];
    float*       out   = (float*)d_out;

    float* qa     = sym(g_qa_buf);
    float* qfull  = sym(g_qfull);
    float* ckvraw = sym(g_ckvraw);
    float* Kc     = sym(g_Kc);
    float* Qc     = sym(g_Qc);
    float* logits = sym(g_logits);
    float* oc     = sym(g_oc);
    float* ao     = sym(g_ao);

    // 1) q_a = hq @ W_qa : (256,1536), K=5120
    gemm_tile<false><<<dim3(RQ / 64, QLEN / 64, 1), 256>>>(
        hq, W_qa, qa, QLEN, RQ, HID, HID, RQ, RQ, 0, 0, 0);

    // 2) rmsnorm(q_a, g_qa)
    rmsnorm_rows<<<QLEN, 256>>>(qa, gqa, RQ);

    // 3) q = qa @ W_qb : (256,24576), K=1536
    gemm_tile<false><<<dim3(QB_COLS / 64, QLEN / 64, 1), 256>>>(
        qa, W_qb, qfull, QLEN, QB_COLS, RQ, RQ, QB_COLS, QB_COLS, 0, 0, 0);

    // 4) ckv_raw = hkv @ W_kva : (4096,576), K=5120
    gemm_tile<false><<<dim3(DQK / 64, SLEN / 64, 1), 256>>>(
        hkv, W_kva, ckvraw, SLEN, DQK, HID, HID, DQK, DQK, 0, 0, 0);

    // 5) K_comb = [rmsnorm(ckv)*g | rope(k_pe)]
    build_K<<<SLEN, 128>>>(ckvraw, gkva, kvpos, Kc);

    // 6) q_c[h] = q_nope[h] @ W_kvb[h, :128, :] : batched (256,512), K=128
    gemm_tile<false><<<dim3(RKV / 64, QLEN / 64, NHEADS), 256>>>(
        qfull, W_kvb, Qc,
        QLEN, RKV, DNOPE,
        QB_COLS, RKV, DQK,
        (long)(DNOPE + DROPE),          // A: +h*192 into q row
        (long)(DNOPE + DNOPE) * RKV,    // B: +h*256*512
        (long)QLEN * DQK);              // C: +h*256*576

    // 7) rope q_pe into Q_comb[...,512:576)
    rope_Q<<<dim3(QLEN, NHEADS), 32>>>(qfull, qpos, Qc);

    // 8) logits[h] = Q_comb[h] @ K_comb^T : batched (256,4096), K=576
    gemm_tile<true><<<dim3(SLEN / 64, QLEN / 64, NHEADS), 256>>>(
        Qc, Kc, logits,
        QLEN, SLEN, DQK,
        DQK, DQK, SLEN,
        (long)QLEN * DQK, 0, (long)QLEN * SLEN);

    // 9) softmax over s (with 1/sqrt(192) scale folded in)
    softmax_rows<<<NHEADS * QLEN, 256>>>(logits, SLEN, 1.0f / sqrtf(192.0f));

    // 10) o_c[h] = attn[h] @ ckv : batched (256,512), K=4096   (B = K_comb cols [0:512))
    gemm_tile<false><<<dim3(RKV / 64, QLEN / 64, NHEADS), 256>>>(
        logits, Kc, oc,
        QLEN, RKV, SLEN,
        SLEN, DQK, RKV,
        (long)QLEN * SLEN, 0, (long)QLEN * RKV);

    // 11) ao[t, h*128+d] = o_c[h] @ out_absorb[h]^T : batched (256,128), K=512
    gemm_tile<true><<<dim3(DNOPE / 64, QLEN / 64, NHEADS), 256>>>(
        oc, W_kvb + (long)DNOPE * RKV, ao,
        QLEN, DNOPE, RKV,
        RKV, RKV, AO_COLS,
        (long)QLEN * RKV, (long)(DNOPE + DNOPE) * RKV, (long)DNOPE);

    // 12) out = ao @ W_o : (256,5120), K=16384
    gemm_tile<false><<<dim3(HID / 64, QLEN / 64, 1), 256>>>(
        ao, W_o, out, QLEN, HID, AO_COLS, AO_COLS, HID, HID, 0, 0, 0);
}

// round 3
// speedup vs baseline: 2.5456x; 2.5456x over previous
#include <cuda_runtime.h>
#include <math.h>
#include <stdint.h>

// ---------------- Problem constants ----------------
#define NHEADS   128
#define DNOPE    128
#define DROPE    64
#define DQK      576
#define RKV      512
#define RQ       1536
#define HID      5120
#define QLEN     256
#define SLEN     4096
#define QB_COLS  24576
#define AO_COLS  16384
#define EPSF     1e-6f

// ---------------- Scratch (device globals) ----------------
__device__ __align__(128) float g_qa_buf [QLEN * RQ];
__device__ __align__(128) float g_qfull  [QLEN * QB_COLS];
__device__ __align__(128) float g_ckvraw [SLEN * DQK];
__device__ __align__(128) float g_Kc     [SLEN * DQK];
__device__ __align__(128) float g_Qc     [(size_t)NHEADS * QLEN * DQK];
__device__ __align__(128) float g_logits [(size_t)NHEADS * QLEN * SLEN];   // 512 MB
__device__ __align__(128) float g_oc     [(size_t)NHEADS * QLEN * RKV];
__device__ __align__(128) float g_ao     [QLEN * AO_COLS];
// transposed operands (B must be [N,K] K-major)
__device__ __align__(128) float g_WqaT   [RQ * HID];
__device__ __align__(128) float g_WqbT   [(size_t)QB_COLS * RQ];
__device__ __align__(128) float g_WkvaT  [DQK * HID];
__device__ __align__(128) float g_WoT    [(size_t)HID * AO_COLS];
__device__ __align__(128) float g_Wkvb6T [(size_t)NHEADS * RKV * DNOPE];
__device__ __align__(128) float g_ckvT   [(size_t)RKV * SLEN];

// ---------------- helpers ----------------
__device__ __forceinline__ uint32_t smem_u32(const void* p) {
    uint32_t a;
    asm("{ .reg .u64 t; cvta.to.shared.u64 t, %1; cvt.u32.u64 %0, t; }" : "=r"(a) : "l"(p));
    return a;
}
__device__ __forceinline__ uint32_t f2tf(float x) {
    uint32_t r;
    asm("cvt.rna.tf32.f32 %0, %1;" : "=r"(r) : "f"(x));
    return r;
}
__device__ __forceinline__ void mma8(float* d, const uint32_t* a, uint32_t b0, uint32_t b1) {
    asm volatile(
        "mma.sync.aligned.m16n8k8.row.col.f32.tf32.tf32.f32 "
        "{%0,%1,%2,%3},{%4,%5,%6,%7},{%8,%9},{%0,%1,%2,%3};"
        : "+f"(d[0]), "+f"(d[1]), "+f"(d[2]), "+f"(d[3])
        : "r"(a[0]), "r"(a[1]), "r"(a[2]), "r"(a[3]), "r"(b0), "r"(b1));
}
__device__ __forceinline__ void cp16(uint32_t dst, const void* src) {
    asm volatile("cp.async.cg.shared.global [%0], [%1], 16;" :: "r"(dst), "l"(src) : "memory");
}

// ---------------- tf32 mma.sync GEMM ----------------
// C[z][bm:bm+128, bn:bn+BN] = A[z] @ B[z]^T, A:[M,K] lda, B:[N,K] ldb, f32 in/out.
// BN = NT*32. K % 32 == 0. 8 warps: 2 (m) x 4 (n), warp tile 64 x (BN/4).
template<int NT>
__global__ void __launch_bounds__(256, 1)
mma_gemm(const float* __restrict__ A, const float* __restrict__ B, float* __restrict__ C,
         int K, int lda, int ldb, int ldc, long sA, long sB, long sC)
{
    constexpr int BN = NT * 32;
    constexpr int PAD = 36;                 // floats per smem row (stride)
    constexpr int A_STAGE = 128 * PAD;      // floats
    constexpr int B_STAGE = BN * PAD;
    constexpr int STAGES = 3;

    extern __shared__ float smf[];
    float* sAb = smf;                       // [STAGES][A_STAGE]
    float* sBb = smf + STAGES * A_STAGE;    // [STAGES][B_STAGE]

    const int tid  = threadIdx.x;
    const int warp = tid >> 5;
    const int lane = tid & 31;
    const int wm = (warp >> 2) * 64;        // 0 / 64
    const int wn = (warp & 3) * (BN / 4);
    const int g  = lane >> 2;               // 0..7
    const int tq = lane & 3;                // 0..3

    const int bm = blockIdx.y * 128;
    const int bn = blockIdx.x * BN;
    A += (long)blockIdx.z * sA + (long)bm * lda;
    B += (long)blockIdx.z * sB + (long)bn * ldb;
    C += (long)blockIdx.z * sC + (long)bm * ldc + bn;

    const int NC = K >> 5;

    float acc[4][NT][4];
#pragma unroll
    for (int i = 0; i < 4; i++)
#pragma unroll
        for (int j = 0; j < NT; j++)
#pragma unroll
            for (int l = 0; l < 4; l++) acc[i][j][l] = 0.f;

    // pipeline prologue
#pragma unroll
    for (int s = 0; s < STAGES - 1; s++) {
        if (s < NC) {
            const float* ga = A + s * 32;
            uint32_t da = smem_u32(sAb + s * A_STAGE);
#pragma unroll
            for (int i = 0; i < 4; i++) {
                int idx = tid + i * 256;
                int r = idx >> 3, c4 = (idx & 7) << 2;
                cp16(da + (uint32_t)(r * PAD + c4) * 4, ga + (long)r * lda + c4);
            }
            const float* gb = B + s * 32;
            uint32_t db = smem_u32(sBb + s * B_STAGE);
#pragma unroll
            for (int i = 0; i < BN / 32; i++) {
                int idx = tid + i * 256;
                int r = idx >> 3, c4 = (idx & 7) << 2;
                cp16(db + (uint32_t)(r * PAD + c4) * 4, gb + (long)r * ldb + c4);
            }
        }
        asm volatile("cp.async.commit_group;" ::: "memory");
    }

    for (int c = 0; c < NC; c++) {
        const int stg = c % STAGES;
        asm volatile("cp.async.wait_group %0;" :: "n"(STAGES - 2) : "memory");
        __syncthreads();

        // prefetch stage c + STAGES - 1
        {
            const int pc = c + STAGES - 1;
            if (pc < NC) {
                const int ps = pc % STAGES;
                const float* ga = A + pc * 32;
                uint32_t da = smem_u32(sAb + ps * A_STAGE);
#pragma unroll
                for (int i = 0; i < 4; i++) {
                    int idx = tid + i * 256;
                    int r = idx >> 3, c4 = (idx & 7) << 2;
                    cp16(da + (uint32_t)(r * PAD + c4) * 4, ga + (long)r * lda + c4);
                }
                const float* gb = B + pc * 32;
                uint32_t db = smem_u32(sBb + ps * B_STAGE);
#pragma unroll
                for (int i = 0; i < BN / 32; i++) {
                    int idx = tid + i * 256;
                    int r = idx >> 3, c4 = (idx & 7) << 2;
                    cp16(db + (uint32_t)(r * PAD + c4) * 4, gb + (long)r * ldb + c4);
                }
            }
            asm volatile("cp.async.commit_group;" ::: "memory");
        }

        const float* As = sAb + stg * A_STAGE;
        const float* Bs = sBb + stg * B_STAGE;

#pragma unroll
        for (int kk = 0; kk < 4; kk++) {
            const int kc = kk * 8;
            uint32_t af[4][4];
#pragma unroll
            for (int mt = 0; mt < 4; mt++) {
                const int r0 = wm + mt * 16 + g;
                af[mt][0] = f2tf(As[r0 * PAD + kc + tq]);
                af[mt][1] = f2tf(As[(r0 + 8) * PAD + kc + tq]);
                af[mt][2] = f2tf(As[r0 * PAD + kc + tq + 4]);
                af[mt][3] = f2tf(As[(r0 + 8) * PAD + kc + tq + 4]);
            }
#pragma unroll
            for (int nt = 0; nt < NT; nt++) {
                const int n0 = wn + nt * 8 + g;
                uint32_t b0 = f2tf(Bs[n0 * PAD + kc + tq]);
                uint32_t b1 = f2tf(Bs[n0 * PAD + kc + tq + 4]);
#pragma unroll
                for (int mt = 0; mt < 4; mt++)
                    mma8(acc[mt][nt], af[mt], b0, b1);
            }
        }
    }

    // epilogue: direct to global
#pragma unroll
    for (int mt = 0; mt < 4; mt++) {
        const int r0 = wm + mt * 16 + g;
#pragma unroll
        for (int nt = 0; nt < NT; nt++) {
            const int c0 = wn + nt * 8 + tq * 2;
            *(float2*)&C[(long)r0 * ldc + c0]       = make_float2(acc[mt][nt][0], acc[mt][nt][1]);
            *(float2*)&C[(long)(r0 + 8) * ldc + c0] = make_float2(acc[mt][nt][2], acc[mt][nt][3]);
        }
    }
}

// ---------------- Transpose: out[z][c][r] = in[z][r*ldin + c] ----------------
__global__ void transpose_k(const float* __restrict__ in, float* __restrict__ out,
                            int R, int ldin, long si, long so)
{
    in  += (long)blockIdx.z * si;
    out += (long)blockIdx.z * so;
    __shared__ float t[32][33];
    const int c0 = blockIdx.x * 32, r0 = blockIdx.y * 32;
    const int x = threadIdx.x, y0 = threadIdx.y;
    #pragma unroll
    for (int i = y0; i < 32; i += 8) t[i][x] = in[(long)(r0 + i) * ldin + c0 + x];
    __syncthreads();
    #pragma unroll
    for (int i = y0; i < 32; i += 8) out[(long)(c0 + i) * R + r0 + x] = t[x][i];
}

// ---------------- RMSNorm (in place) ----------------
__global__ void rmsnorm_rows(float* __restrict__ X, const float* __restrict__ g, int cols)
{
    const long row = blockIdx.x;
    float* x = X + row * (long)cols;
    const int tid = threadIdx.x;
    float ss = 0.f;
    for (int c = tid; c < cols; c += blockDim.x) { float v = x[c]; ss += v * v; }
    __shared__ float red[256];
    red[tid] = ss; __syncthreads();
    for (int s = 128; s > 0; s >>= 1) { if (tid < s) red[tid] += red[tid + s]; __syncthreads(); }
    const float inv = rsqrtf(red[0] / (float)cols + EPSF);
    for (int c = tid; c < cols; c += blockDim.x) x[c] = x[c] * inv * g[c];
}

// ---------------- Build K_comb ----------------
__global__ void build_K(const float* __restrict__ raw, const float* __restrict__ g,
                        const int* __restrict__ kvpos, float* __restrict__ Kc)
{
    const int s = blockIdx.x;
    const float* r = raw + (long)s * DQK;
    float* k = Kc + (long)s * DQK;
    const int tid = threadIdx.x;   // 128

    float ss = 0.f;
    for (int c = tid; c < RKV; c += 128) { float v = r[c]; ss += v * v; }
    __shared__ float red[128];
    red[tid] = ss; __syncthreads();
    for (int st = 64; st > 0; st >>= 1) { if (tid < st) red[tid] += red[tid + st]; __syncthreads(); }
    const float inv = rsqrtf(red[0] / (float)RKV + EPSF);
    for (int c = tid; c < RKV; c += 128) k[c] = r[c] * inv * g[c];

    if (tid < 32) {
        const int j = tid;
        const float x0 = r[RKV + 2 * j];
        const float x1 = r[RKV + 2 * j + 1];
        const float pos = (float)kvpos[s];
        const float invf = powf(10000.f, -(float)j / 32.f);
        float cs, sn; sincosf(pos * invf, &sn, &cs);
        k[RKV + j]      = x0 * cs - x1 * sn;
        k[RKV + 32 + j] = x0 * sn + x1 * cs;
    }
}

// ---------------- RoPE for q_pe ----------------
__global__ void rope_Q(const float* __restrict__ qfull, const int* __restrict__ qpos,
                       float* __restrict__ Qc)
{
    const int t = blockIdx.x;
    const int h = blockIdx.y;
    const int j = threadIdx.x;   // 32
    const float* src = qfull + (long)t * QB_COLS + h * (DNOPE + DROPE) + DNOPE;
    const float x0 = src[2 * j];
    const float x1 = src[2 * j + 1];
    const float pos = (float)qpos[t];
    const float invf = powf(10000.f, -(float)j / 32.f);
    float cs, sn; sincosf(pos * invf, &sn, &cs);
    float* dst = Qc + ((long)h * QLEN + t) * DQK + RKV;
    dst[j]      = x0 * cs - x1 * sn;
    dst[32 + j] = x0 * sn + x1 * cs;
}

// ---------------- Row softmax ----------------
__global__ void softmax_rows(float* __restrict__ X, int cols, float scale)
{
    const long row = blockIdx.x;
    float* x = X + row * (long)cols;
    const int tid = threadIdx.x;   // 256
    __shared__ float red[256];

    float m = -INFINITY;
    for (int c = tid; c < cols; c += 256) m = fmaxf(m, x[c]);
    red[tid] = m; __syncthreads();
    for (int s = 128; s > 0; s >>= 1) { if (tid < s) red[tid] = fmaxf(red[tid], red[tid + s]); __syncthreads(); }
    m = red[0]; __syncthreads();

    float sum = 0.f;
    for (int c = tid; c < cols; c += 256) {
        float p = __expf((x[c] - m) * scale);
        x[c] = p;
        sum += p;
    }
    red[tid] = sum; __syncthreads();
    for (int s = 128; s > 0; s >>= 1) { if (tid < s) red[tid] += red[tid + s]; __syncthreads(); }
    const float invs = 1.f / red[0];
    for (int c = tid; c < cols; c += 256) x[c] *= invs;
}

// ---------------- Launch ----------------
static inline float* sym(const void* s)
{
    void* p = nullptr;
    cudaGetSymbolAddress(&p, s);
    return (float*)p;
}

static inline size_t mma_smem(int NT) {
    return (size_t)3 * (128 + NT * 32) * 36 * 4;
}

static void mma(const float* A, const float* B, float* C,
                int M, int N, int K, int lda, int ldb, int ldc,
                long sA, long sB, long sC, int nTile, int Z)
{
    dim3 grid(N / nTile, M / 128, Z);
    if (nTile == 256)
        mma_gemm<8><<<grid, 256, mma_smem(8)>>>(A, B, C, K, lda, ldb, ldc, sA, sB, sC);
    else if (nTile == 192)
        mma_gemm<6><<<grid, 256, mma_smem(6)>>>(A, B, C, K, lda, ldb, ldc, sA, sB, sC);
    else
        mma_gemm<4><<<grid, 256, mma_smem(4)>>>(A, B, C, K, lda, ldb, ldc, sA, sB, sC);
}

extern "C" void kernel_launch(void* const* d_in, const int* in_sizes, int n_in,
                              void* d_out, int out_size)
{
    const float* hq    = (const float*)d_in[0];
    const float* hkv   = (const float*)d_in[1];
    const float* W_qa  = (const float*)d_in[2];
    const float* gqa   = (const float*)d_in[3];
    const float* W_qb  = (const float*)d_in[4];
    const float* W_kva = (const float*)d_in[5];
    const float* gkva  = (const float*)d_in[6];
    const float* W_kvb = (const float*)d_in[7];
    const float* W_o   = (const float*)d_in[8];
    const int*   qpos  = (const int*)d_in[9];
    const int*   kvpos = (const int*)d_in[10];
    float*       out   = (float*)d_out;

    float* qa     = sym(g_qa_buf);
    float* qfull  = sym(g_qfull);
    float* ckvraw = sym(g_ckvraw);
    float* Kc     = sym(g_Kc);
    float* Qc     = sym(g_Qc);
    float* logits = sym(g_logits);
    float* oc     = sym(g_oc);
    float* ao     = sym(g_ao);
    float* WqaT   = sym(g_WqaT);
    float* WqbT   = sym(g_WqbT);
    float* WkvaT  = sym(g_WkvaT);
    float* WoT    = sym(g_WoT);
    float* Wkvb6T = sym(g_Wkvb6T);
    float* ckvT   = sym(g_ckvT);

    static bool attr_set = false;
    if (!attr_set) {
        cudaFuncSetAttribute(mma_gemm<8>, cudaFuncAttributeMaxDynamicSharedMemorySize, (int)mma_smem(8));
        cudaFuncSetAttribute(mma_gemm<6>, cudaFuncAttributeMaxDynamicSharedMemorySize, (int)mma_smem(6));
        cudaFuncSetAttribute(mma_gemm<4>, cudaFuncAttributeMaxDynamicSharedMemorySize, (int)mma_smem(4));
        attr_set = true;
    }

    // weight transposes (independent of activations)
    transpose_k<<<dim3(RQ / 32, HID / 32, 1),       dim3(32, 8)>>>(W_qa,  WqaT,  HID,  RQ,      0, 0);
    transpose_k<<<dim3(QB_COLS / 32, RQ / 32, 1),   dim3(32, 8)>>>(W_qb,  WqbT,  RQ,   QB_COLS, 0, 0);
    transpose_k<<<dim3(DQK / 32, HID / 32, 1),      dim3(32, 8)>>>(W_kva, WkvaT, HID,  DQK,     0, 0);
    transpose_k<<<dim3(HID / 32, AO_COLS / 32, 1),  dim3(32, 8)>>>(W_o,   WoT,   AO_COLS, HID,  0, 0);
    transpose_k<<<dim3(RKV / 32, DNOPE / 32, NHEADS), dim3(32, 8)>>>(W_kvb, Wkvb6T, DNOPE, RKV,
                                                                    (long)(DNOPE + DNOPE) * RKV,
                                                                    (long)RKV * DNOPE);

    // 1) qa = hq @ W_qa : (256,1536), K=5120
    mma(hq, WqaT, qa, QLEN, RQ, HID, HID, HID, RQ, 0, 0, 0, 256, 1);
    // 2) rmsnorm
    rmsnorm_rows<<<QLEN, 256>>>(qa, gqa, RQ);
    // 3) qfull = qa @ W_qb : (256,24576), K=1536
    mma(qa, WqbT, qfull, QLEN, QB_COLS, RQ, RQ, RQ, QB_COLS, 0, 0, 0, 256, 1);
    // 4) ckvraw = hkv @ W_kva : (4096,576), K=5120
    mma(hkv, WkvaT, ckvraw, SLEN, DQK, HID, HID, HID, DQK, 0, 0, 0, 192, 1);
    // 5) K_comb
    build_K<<<SLEN, 128>>>(ckvraw, gkva, kvpos, Kc);
    // ckvT[c][s] = Kc[s][c], c<512
    transpose_k<<<dim3(RKV / 32, SLEN / 32, 1), dim3(32, 8)>>>(Kc, ckvT, SLEN, DQK, 0, 0);
    // 6) q_c[h] = q_nope[h] @ q_absorb[h]^T : batched (256,512), K=128
    mma(qfull, Wkvb6T, Qc, QLEN, RKV, DNOPE,
        QB_COLS, DNOPE, DQK,
        (long)(DNOPE + DROPE), (long)RKV * DNOPE, (long)QLEN * DQK, 256, NHEADS);
    // 7) rope q_pe
    rope_Q<<<dim3(QLEN, NHEADS), 32>>>(qfull, qpos, Qc);
    // 8) logits[h] = Q_comb[h] @ K_comb^T : batched (256,4096), K=576
    mma(Qc, Kc, logits, QLEN, SLEN, DQK,
        DQK, DQK, SLEN,
        (long)QLEN * DQK, 0, (long)QLEN * SLEN, 256, NHEADS);
    // 9) softmax
    softmax_rows<<<NHEADS * QLEN, 256>>>(logits, SLEN, 1.0f / sqrtf(192.0f));
    // 10) oc[h] = P[h] @ ckvT^T : batched (256,512), K=4096
    mma(logits, ckvT, oc, QLEN, RKV, SLEN,
        SLEN, SLEN, RKV,
        (long)QLEN * SLEN, 0, (long)QLEN * RKV, 256, NHEADS);
    // 11) ao[:, h*128:] = oc[h] @ out_absorb[h]^T : batched (256,128), K=512
    mma(oc, W_kvb + (long)DNOPE * RKV, ao, QLEN, DNOPE, RKV,
        RKV, RKV, AO_COLS,
        (long)QLEN * RKV, (long)(DNOPE + DNOPE) * RKV, (long)DNOPE, 128, NHEADS);
    // 12) out = ao @ W_o : (256,5120), K=16384
    mma(ao, WoT, out, QLEN, HID, AO_COLS, AO_COLS, AO_COLS, HID, 0, 0, 0, 256, 1);
}